// round 16
// baseline (speedup 1.0000x reference)
#include <cuda_runtime.h>
#include <cuda_fp16.h>
#include <math.h>
#include <stdint.h>

// ---------------- problem constants ----------------
#define BATCH  32
#define HEADS  12
#define SEQ    512
#define LHALF  256
#define DMODEL 768
#define HH     384          // hidden per direction
#define G4     1536         // 4*HH gates
#define DIN    1536         // 2*DMODEL LSTM input
#define BH     384          // BATCH*HEADS
#define TT     6            // SLIDER
#define EPSV   1e-9f

// ---------------- device scratch (no allocs allowed) ----------------
__device__ int    g_master[BH * 2];
__device__ __half g_gatesX[(size_t)BH * TT * 2 * G4];   // fp16, gate-interleaved cols (4*j+gate), bias folded
__device__ float  g_c[(size_t)2 * BH * HH];
__device__ float  g_compose[(size_t)BH * TT * DMODEL];
__device__ float  g_lrep[(size_t)BATCH * DMODEL];

// fp16 operands (weights gate-interleaved rows: 4*j+gate)
__device__ __half g_slide[(size_t)BH * TT * DIN];
__device__ __half g_wih[(size_t)2 * G4 * DIN];
__device__ __half g_whh[(size_t)2 * G4 * HH];
__device__ __half g_hb[(size_t)2 * BH * HH];       // [dir][n][j]
__device__ float  g_bias[2 * G4];                  // gate-interleaved

// ---------------- PTX helpers (baseline PTX only) ----------------
__device__ __forceinline__ uint32_t smem_u32(const void* p) {
    uint32_t a;
    asm("{ .reg .u64 t; cvta.to.shared.u64 t, %1; cvt.u32.u64 %0, t; }" : "=r"(a) : "l"(p));
    return a;
}

#define CP_ASYNC16(sm, gm) \
    asm volatile("cp.async.cg.shared.global [%0], [%1], 16;" :: "r"(sm), "l"(gm) : "memory")
#define CP_COMMIT() asm volatile("cp.async.commit_group;" ::: "memory")
#define CP_WAIT0()  asm volatile("cp.async.wait_group 0;" ::: "memory")

#define LDSM_X4(r0, r1, r2, r3, addr) \
    asm volatile("ldmatrix.sync.aligned.m8n8.x4.shared.b16 {%0,%1,%2,%3}, [%4];" \
        : "=r"(r0), "=r"(r1), "=r"(r2), "=r"(r3) : "r"(addr))

#define MMA_F16(c0, c1, c2, c3, a0, a1, a2, a3, b0, b1) \
    asm volatile("mma.sync.aligned.m16n8k16.row.col.f32.f16.f16.f32 " \
        "{%0,%1,%2,%3}, {%4,%5,%6,%7}, {%8,%9}, {%0,%1,%2,%3};" \
        : "+f"(c0), "+f"(c1), "+f"(c2), "+f"(c3) \
        : "r"(a0), "r"(a1), "r"(a2), "r"(a3), "r"(b0), "r"(b1))

// ---------------- helpers ----------------
__device__ __forceinline__ float sigf(float x) { return 1.0f / (1.0f + expf(-x)); }

__device__ __forceinline__ int window_start(int pos) {
    pos = min(max(pos, 1), LHALF - 2);
    int l = TT / 2;
    if (pos - TT / 2 <= 0) l = pos - 1;
    int r = TT - l;
    if (pos + r >= LHALF - 1) l = TT - (LHALF - pos - 2);
    return pos - l;
}

// ---------------- K1: masters (deep-MLP row sums) ----------------
__global__ void masters_kernel(const float* __restrict__ att, const int* __restrict__ sents) {
    int bid  = blockIdx.x;
    int half = bid & 1;
    int bh   = bid >> 1;
    int b    = bh / HEADS;

    __shared__ unsigned char seps[LHALF];
    __shared__ float rowsum[LHALF];

    int tid = threadIdx.x;
    {
        int j = half * LHALF + tid;
        seps[tid] = (sents[b * SEQ + j] == 102) ? 1 : 0;
    }
    __syncthreads();

    const float* base = att + ((size_t)bh * SEQ + (size_t)half * LHALF) * SEQ + (size_t)half * LHALF;

    int warp = tid >> 5, lane = tid & 31;
    #pragma unroll
    for (int rr = 0; rr < 32; rr += 4) {
        int row = warp * 32 + rr;
        const float4* r0 = (const float4*)(base + (size_t)(row + 0) * SEQ);
        const float4* r1 = (const float4*)(base + (size_t)(row + 1) * SEQ);
        const float4* r2 = (const float4*)(base + (size_t)(row + 2) * SEQ);
        const float4* r3 = (const float4*)(base + (size_t)(row + 3) * SEQ);
        float4 v0a = __ldg(r0 + lane), v0b = __ldg(r0 + lane + 32);
        float4 v1a = __ldg(r1 + lane), v1b = __ldg(r1 + lane + 32);
        float4 v2a = __ldg(r2 + lane), v2b = __ldg(r2 + lane + 32);
        float4 v3a = __ldg(r3 + lane), v3b = __ldg(r3 + lane + 32);

        int ja = lane * 4, jb = (lane + 32) * 4;
        float s0 = (seps[ja] ? EPSV : v0a.x) + (seps[ja+1] ? EPSV : v0a.y)
                 + (seps[ja+2] ? EPSV : v0a.z) + (seps[ja+3] ? EPSV : v0a.w)
                 + (seps[jb] ? EPSV : v0b.x) + (seps[jb+1] ? EPSV : v0b.y)
                 + (seps[jb+2] ? EPSV : v0b.z) + (seps[jb+3] ? EPSV : v0b.w);
        float s1 = (seps[ja] ? EPSV : v1a.x) + (seps[ja+1] ? EPSV : v1a.y)
                 + (seps[ja+2] ? EPSV : v1a.z) + (seps[ja+3] ? EPSV : v1a.w)
                 + (seps[jb] ? EPSV : v1b.x) + (seps[jb+1] ? EPSV : v1b.y)
                 + (seps[jb+2] ? EPSV : v1b.z) + (seps[jb+3] ? EPSV : v1b.w);
        float s2 = (seps[ja] ? EPSV : v2a.x) + (seps[ja+1] ? EPSV : v2a.y)
                 + (seps[ja+2] ? EPSV : v2a.z) + (seps[ja+3] ? EPSV : v2a.w)
                 + (seps[jb] ? EPSV : v2b.x) + (seps[jb+1] ? EPSV : v2b.y)
                 + (seps[jb+2] ? EPSV : v2b.z) + (seps[jb+3] ? EPSV : v2b.w);
        float s3 = (seps[ja] ? EPSV : v3a.x) + (seps[ja+1] ? EPSV : v3a.y)
                 + (seps[ja+2] ? EPSV : v3a.z) + (seps[ja+3] ? EPSV : v3a.w)
                 + (seps[jb] ? EPSV : v3b.x) + (seps[jb+1] ? EPSV : v3b.y)
                 + (seps[jb+2] ? EPSV : v3b.z) + (seps[jb+3] ? EPSV : v3b.w);

        #pragma unroll
        for (int off = 16; off > 0; off >>= 1) {
            s0 += __shfl_down_sync(0xffffffffu, s0, off);
            s1 += __shfl_down_sync(0xffffffffu, s1, off);
            s2 += __shfl_down_sync(0xffffffffu, s2, off);
            s3 += __shfl_down_sync(0xffffffffu, s3, off);
        }
        if (lane == 0) {
            rowsum[row]     = s0;
            rowsum[row + 1] = s1;
            rowsum[row + 2] = s2;
            rowsum[row + 3] = s3;
        }
    }
    __syncthreads();

    __shared__ float bv[LHALF];
    __shared__ int   bix[LHALF];
    bv[tid]  = rowsum[tid];
    bix[tid] = tid;
    __syncthreads();
    for (int off = 128; off > 0; off >>= 1) {
        if (tid < off) {
            float vo = bv[tid + off];
            int   io = bix[tid + off];
            if (vo > bv[tid] || (vo == bv[tid] && io < bix[tid])) { bv[tid] = vo; bix[tid] = io; }
        }
        __syncthreads();
    }
    if (tid == 0) g_master[bh * 2 + half] = bix[0];
}

// ---------------- K2: gather windows -> slide (fp16) ----------------
__global__ void build_slide(const float* __restrict__ logits, const int* __restrict__ mask) {
    int bh = blockIdx.x;
    int b  = bh / HEADS;
    __shared__ int sa, sb;
    if (threadIdx.x == 0) {
        sa = window_start(g_master[bh * 2 + 0]);
        sb = window_start(g_master[bh * 2 + 1]);
    }
    __syncthreads();

    for (int idx = threadIdx.x; idx < TT * DIN; idx += blockDim.x) {
        int t = idx / DIN, f = idx % DIN;
        float v;
        if (f < DMODEL) {
            int row = sa + t;
            v = (mask[b * SEQ + row] == 0) ? EPSV
                : logits[((size_t)b * SEQ + row) * DMODEL + f];
        } else {
            int row = LHALF + sb + t;
            v = (mask[b * SEQ + row] == 0) ? EPSV
                : logits[((size_t)b * SEQ + row) * DMODEL + (f - DMODEL)];
        }
        g_slide[(size_t)bh * (TT * DIN) + idx] = __float2half(v);
    }
}

// ---------------- K3: fused prep (fp16 weights with gate interleave + bias) ----------------
#define NW ((size_t)G4 * DIN)    // 2359296
#define NH ((size_t)G4 * HH)     // 589824
#define PREP_TOTAL (2 * NW + 2 * NH + 2 * G4)

__global__ void prep_kernel(const float* __restrict__ wih_f, const float* __restrict__ wih_r,
                            const float* __restrict__ whh_f, const float* __restrict__ whh_r,
                            const float* __restrict__ bihf, const float* __restrict__ bhhf,
                            const float* __restrict__ bihr, const float* __restrict__ bhhr) {
    size_t i = (size_t)blockIdx.x * blockDim.x + threadIdx.x;
    if (i >= PREP_TOTAL) return;
    if (i < 2 * NW + 2 * NH) {
        const float* src;
        __half* dh;
        size_t off;
        int kdim;
        if (i < NW)               { src = wih_f; dh = g_wih;      off = i;                kdim = DIN; }
        else if (i < 2 * NW)      { src = wih_r; dh = g_wih + NW; off = i - NW;           kdim = DIN; }
        else if (i < 2 * NW + NH) { src = whh_f; dh = g_whh;      off = i - 2 * NW;       kdim = HH;  }
        else                      { src = whh_r; dh = g_whh + NH; off = i - 2 * NW - NH;  kdim = HH;  }
        size_t row = off / kdim, k = off % kdim;
        int gate = (int)(row / HH), j = (int)(row % HH);
        size_t drow = (size_t)(4 * j + gate);
        dh[drow * kdim + k] = __float2half(src[off]);
    } else {
        size_t q = i - (2 * NW + 2 * NH);      // [0, 2*G4)
        int dir = (int)(q / G4);
        int r   = (int)(q % G4);
        int gate = r / HH, j = r % HH;
        float v = dir ? (bihr[r] + bhhr[r]) : (bihf[r] + bhhf[r]);
        g_bias[dir * G4 + 4 * j + gate] = v;
    }
}

// ---------------- GEMM core: tile 64(M) x 192(N), fp16 single product, 2 CTAs/SM ----------------
// Chunk layout: A(8KB) | B(24KB) = 32KB, double buffered.
#define BK          64
#define BN          192
#define A_CHUNK     8192           // 64 rows x 128B
#define B_CHUNK     24576          // 192 rows x 128B
#define BUF_BYTES   (A_CHUNK + B_CHUNK)       // 32768
#define GM_SMEM     (1024 + 2 * BUF_BYTES)    // 66560
#define STG_STRIDE  196                        // padded fp32 row stride for staging

__device__ __forceinline__ void gemm_core(
    const __half* A, const __half* B,
    int bm, int bn, int K, int NC,
    char* smem_raw, uint32_t tiles_u,
    int tid, int lane, int wm, int wn,
    float acc[2][6][4])
{
    int Kd8 = K >> 3;

    auto load_chunk = [&](int c, int buf) {
        int k0 = c * BK;
        uint32_t bufu = tiles_u + buf * BUF_BYTES;
        {
            const uint4* gp = (const uint4*)(A + (size_t)bm * K + k0);
            #pragma unroll
            for (int i = 0; i < 2; i++) {
                int u = tid + i * 256;
                int r = u >> 3, c16 = u & 7;
                const uint4* ga = gp + (size_t)r * Kd8 + c16;
                uint32_t off = (uint32_t)(r * 128 + c16 * 16);
                uint32_t sw = off ^ ((off >> 3) & 0x70);
                CP_ASYNC16(bufu + sw, ga);
            }
        }
        {
            const uint4* gp = (const uint4*)(B + (size_t)bn * K + k0);
            uint32_t tb = bufu + A_CHUNK;
            #pragma unroll
            for (int i = 0; i < 6; i++) {
                int u = tid + i * 256;
                int r = u >> 3, c16 = u & 7;
                const uint4* ga = gp + (size_t)r * Kd8 + c16;
                uint32_t off = (uint32_t)(r * 128 + c16 * 16);
                uint32_t sw = off ^ ((off >> 3) & 0x70);
                CP_ASYNC16(tb + sw, ga);
            }
        }
    };

    load_chunk(0, 0);
    CP_COMMIT();

    for (int c = 0; c < NC; c++) {
        CP_WAIT0();
        __syncthreads();
        if (c + 1 < NC) { load_chunk(c + 1, (c + 1) & 1); CP_COMMIT(); }

        uint32_t base = tiles_u + (c & 1) * BUF_BYTES;
        uint32_t a_base = base;
        uint32_t b_base = base + A_CHUNK;

        #pragma unroll
        for (int ks = 0; ks < 4; ks++) {
            uint32_t a[2][4];
            #pragma unroll
            for (int mt = 0; mt < 2; mt++) {
                uint32_t r = wm + mt * 16 + (lane & 15);
                uint32_t coloff = ks * 32 + ((lane >> 4) & 1) * 16;
                uint32_t off = r * 128 + coloff;
                uint32_t sw = off ^ ((off >> 3) & 0x70);
                LDSM_X4(a[mt][0], a[mt][1], a[mt][2], a[mt][3], a_base + sw);
            }
            uint32_t b[6][2];
            #pragma unroll
            for (int h = 0; h < 3; h++) {
                uint32_t r = wn + h * 16 + (lane & 7) + ((lane >> 4) << 3);
                uint32_t coloff = ks * 32 + ((lane >> 3) & 1) * 16;
                uint32_t off = r * 128 + coloff;
                uint32_t sw = off ^ ((off >> 3) & 0x70);
                uint32_t r0, r1, r2, r3;
                LDSM_X4(r0, r1, r2, r3, b_base + sw);
                b[2 * h][0] = r0; b[2 * h][1] = r1;
                b[2 * h + 1][0] = r2; b[2 * h + 1][1] = r3;
            }
            #pragma unroll
            for (int mt = 0; mt < 2; mt++)
                #pragma unroll
                for (int nt = 0; nt < 6; nt++)
                    MMA_F16(acc[mt][nt][0], acc[mt][nt][1], acc[mt][nt][2], acc[mt][nt][3],
                            a[mt][0], a[mt][1], a[mt][2], a[mt][3],
                            b[nt][0], b[nt][1]);
        }
        __syncthreads();
    }
}

// ---------------- K4: input GEMM (tile 64x192, 2 CTAs/SM) ----------------
__global__ __launch_bounds__(256, 2) void input_gemm_hmma() {
    extern __shared__ char smem_raw[];
    uint32_t smem_u = smem_u32(smem_raw);
    uint32_t tiles_u = (smem_u + 1023) & ~1023u;

    int tid = threadIdx.x, wid = tid >> 5, lane = tid & 31;
    int wm = (wid & 1) * 32, wn = (wid >> 1) * 48;
    int bm = blockIdx.y * 64;
    int bn = blockIdx.x * BN;

    float acc[2][6][4];
    #pragma unroll
    for (int i = 0; i < 2; i++)
        #pragma unroll
        for (int j = 0; j < 6; j++)
            #pragma unroll
            for (int q = 0; q < 4; q++) acc[i][j][q] = 0.0f;

    gemm_core(g_slide, g_wih, bm, bn, DIN, DIN / BK,
              smem_raw, tiles_u, tid, lane, wm, wn, acc);

    #pragma unroll
    for (int mt = 0; mt < 2; mt++) {
        #pragma unroll
        for (int nt = 0; nt < 6; nt++) {
            int row = bm + wm + mt * 16 + (lane >> 2);
            int col = bn + wn + nt * 8 + (lane & 3) * 2;
            float b0 = g_bias[col], b1 = g_bias[col + 1];
            __half2 v0 = __floats2half2_rn(acc[mt][nt][0] + b0, acc[mt][nt][1] + b1);
            __half2 v1 = __floats2half2_rn(acc[mt][nt][2] + b0, acc[mt][nt][3] + b1);
            *(__half2*)(g_gatesX + (size_t)row * (2 * G4) + col) = v0;
            *(__half2*)(g_gatesX + (size_t)(row + 8) * (2 * G4) + col) = v1;
        }
    }
}

// ---------------- K5: fused recurrent GEMM + LSTM pointwise (steps 1..5) ----------------
// Grid dim3(G4/BN=8, BH/64=6, 2). Tile: batch rows [bm,bm+64), gate cols [bn,bn+192)
// = hidden units [bn/4, bn/4+48). Epilogue stages acc to SMEM, then each thread
// processes 12 complete hidden units with coalesced float4/half2 accesses.
__global__ __launch_bounds__(256, 2) void fused_rec_step(int s) {
    extern __shared__ char smem_raw[];
    uint32_t smem_u = smem_u32(smem_raw);
    uint32_t tiles_u = (smem_u + 1023) & ~1023u;
    float* sc = (float*)(smem_raw + (tiles_u - smem_u));   // staging (reuses buffers)

    int dir = blockIdx.z;
    const __half* A = g_hb + (size_t)dir * BH * HH;
    const __half* B = g_whh + (size_t)dir * G4 * HH;

    int tid = threadIdx.x, wid = tid >> 5, lane = tid & 31;
    int wm = (wid & 1) * 32, wn = (wid >> 1) * 48;
    int bm = blockIdx.y * 64;
    int bn = blockIdx.x * BN;

    float acc[2][6][4];
    #pragma unroll
    for (int i = 0; i < 2; i++)
        #pragma unroll
        for (int j = 0; j < 6; j++)
            #pragma unroll
            for (int q = 0; q < 4; q++) acc[i][j][q] = 0.0f;

    gemm_core(A, B, bm, bn, HH, HH / BK,
              smem_raw, tiles_u, tid, lane, wm, wn, acc);
    // gemm_core ends with __syncthreads(); safe to overwrite buffers.

    #pragma unroll
    for (int mt = 0; mt < 2; mt++) {
        #pragma unroll
        for (int nt = 0; nt < 6; nt++) {
            int rl = wm + mt * 16 + (lane >> 2);
            int cl = wn + nt * 8 + (lane & 3) * 2;
            sc[rl * STG_STRIDE + cl]           = acc[mt][nt][0];
            sc[rl * STG_STRIDE + cl + 1]       = acc[mt][nt][1];
            sc[(rl + 8) * STG_STRIDE + cl]     = acc[mt][nt][2];
            sc[(rl + 8) * STG_STRIDE + cl + 1] = acc[mt][nt][3];
        }
    }
    __syncthreads();

    int t = dir ? (TT - 1 - s) : s;
    int jbase = bn >> 2;                 // first hidden unit of this tile

    #pragma unroll
    for (int u0 = 0; u0 < 12; u0++) {
        int u = tid + u0 * 256;          // [0, 3072)
        int nl = u / 48, jl = u % 48;
        int n = bm + nl;
        int j = jbase + jl;

        float4 gr = *(const float4*)(sc + nl * STG_STRIDE + 4 * jl);
        const __half2* gp = (const __half2*)(g_gatesX + ((size_t)(n * TT + t)) * (2 * G4)
                                             + (size_t)dir * G4 + 4 * j);
        float2 p0 = __half22float2(gp[0]);
        float2 p1 = __half22float2(gp[1]);
        float gi = p0.x + gr.x;
        float gf = p0.y + gr.y;
        float gg = p1.x + gr.z;
        float go = p1.y + gr.w;

        int idx = dir * (BH * HH) + n * HH + j;
        float c = sigf(gf) * g_c[idx] + sigf(gi) * tanhf(gg);
        float h = sigf(go) * tanhf(c);
        g_c[idx] = c;
        g_hb[idx] = __float2half(h);
        g_compose[((size_t)n * TT + t) * DMODEL + dir * HH + j] = h;
    }
}

// ---------------- K6: LSTM step 0 (no recurrent term; h0 = c0 = 0) ----------------
__global__ void lstm0_kernel() {
    int idx = blockIdx.x * blockDim.x + threadIdx.x;
    if (idx >= 2 * BH * HH) return;
    int dir = idx / (BH * HH);
    int r   = idx % (BH * HH);
    int n   = r / HH;
    int j   = r % HH;
    int t   = dir ? (TT - 1) : 0;

    const __half2* gp = (const __half2*)(g_gatesX + ((size_t)(n * TT + t)) * (2 * G4)
                                         + (size_t)dir * G4 + 4 * j);
    float2 p0 = __half22float2(gp[0]);
    float2 p1 = __half22float2(gp[1]);
    float c = sigf(p0.x) * tanhf(p1.x);
    float h = sigf(p1.y) * tanhf(c);
    g_c[idx] = c;
    g_hb[idx] = __float2half(h);
    g_compose[((size_t)n * TT + t) * DMODEL + dir * HH + j] = h;
}

// ---------------- K7: logits_rep (parallelized, deep ILP) ----------------
__global__ void logits_rep_kernel(const float* __restrict__ logits, const int* __restrict__ mask) {
    int b = blockIdx.x;
    int d = blockIdx.y * 128 + threadIdx.x;
    int tid = threadIdx.x;

    __shared__ unsigned char repl[SEQ];
    for (int i = tid; i < SEQ; i += blockDim.x) repl[i] = 0;
    __syncthreads();
    if (tid < 2 * HEADS) {
        int h = tid >> 1, half = tid & 1;
        int st = window_start(g_master[(b * HEADS + h) * 2 + half]);
        int base = half * LHALF + st;
        for (int k = 0; k < TT; k++) repl[base + k] = 1;
    }
    __syncthreads();
    for (int sPos = tid; sPos < SEQ; sPos += blockDim.x)
        repl[sPos] = (repl[sPos] && mask[b * SEQ + sPos] == 0) ? 1 : 0;
    __syncthreads();

    float a0 = 0.f, a1 = 0.f, a2 = 0.f, a3 = 0.f;
    const float* lp = logits + (size_t)b * SEQ * DMODEL + d;
    for (int sPos = 0; sPos < SEQ; sPos += 8) {
        float v0 = __ldg(lp + (size_t)(sPos + 0) * DMODEL);
        float v1 = __ldg(lp + (size_t)(sPos + 1) * DMODEL);
        float v2 = __ldg(lp + (size_t)(sPos + 2) * DMODEL);
        float v3 = __ldg(lp + (size_t)(sPos + 3) * DMODEL);
        float v4 = __ldg(lp + (size_t)(sPos + 4) * DMODEL);
        float v5 = __ldg(lp + (size_t)(sPos + 5) * DMODEL);
        float v6 = __ldg(lp + (size_t)(sPos + 6) * DMODEL);
        float v7 = __ldg(lp + (size_t)(sPos + 7) * DMODEL);
        a0 += repl[sPos]     ? EPSV : v0;
        a1 += repl[sPos + 1] ? EPSV : v1;
        a2 += repl[sPos + 2] ? EPSV : v2;
        a3 += repl[sPos + 3] ? EPSV : v3;
        a0 += repl[sPos + 4] ? EPSV : v4;
        a1 += repl[sPos + 5] ? EPSV : v5;
        a2 += repl[sPos + 6] ? EPSV : v6;
        a3 += repl[sPos + 7] ? EPSV : v7;
    }
    g_lrep[(size_t)b * DMODEL + d] = (a0 + a1 + a2 + a3) * (1.0f / (float)SEQ);
}

// ---------------- K8: final FC + softmax ----------------
__global__ void final_kernel(const float* __restrict__ fcw, const float* __restrict__ fcb,
                             float* __restrict__ out) {
    int b = blockIdx.x;
    int tid = threadIdx.x;
    const int NF = DMODEL * (HEADS + 1);
    float a0 = 0.0f, a1 = 0.0f;

    for (int j = tid; j < NF; j += 256) {
        float x;
        if (j < HEADS * DMODEL) {
            int h = j / DMODEL, d = j % DMODEL;
            int n = b * HEADS + h;
            const float* cp = g_compose + (size_t)n * TT * DMODEL + d;
            float s = 0.0f;
            #pragma unroll
            for (int t = 0; t < TT; t++) s += cp[(size_t)t * DMODEL];
            x = s * (1.0f / (float)TT);
        } else {
            x = g_lrep[(size_t)b * DMODEL + (j - HEADS * DMODEL)];
        }
        a0 += x * fcw[j];
        a1 += x * fcw[NF + j];
    }

    __shared__ float s0[256], s1[256];
    s0[tid] = a0; s1[tid] = a1;
    __syncthreads();
    for (int off = 128; off > 0; off >>= 1) {
        if (tid < off) { s0[tid] += s0[tid + off]; s1[tid] += s1[tid + off]; }
        __syncthreads();
    }
    if (tid == 0) {
        float l0 = s0[0] + fcb[0], l1 = s1[0] + fcb[1];
        float m = fmaxf(l0, l1);
        float e0 = expf(l0 - m), e1 = expf(l1 - m);
        float inv = 1.0f / (e0 + e1);
        out[b * 2 + 0] = e0 * inv;
        out[b * 2 + 1] = e1 * inv;
    }
}

// ---------------- launch ----------------
extern "C" void kernel_launch(void* const* d_in, const int* in_sizes, int n_in,
                              void* d_out, int out_size) {
    const int*   sents = (const int*)d_in[0];
    const float* att   = (const float*)d_in[1];
    const float* logits= (const float*)d_in[2];
    const int*   mask  = (const int*)d_in[3];
    const float* wih_f = (const float*)d_in[4];
    const float* whh_f = (const float*)d_in[5];
    const float* bih_f = (const float*)d_in[6];
    const float* bhh_f = (const float*)d_in[7];
    const float* wih_r = (const float*)d_in[8];
    const float* whh_r = (const float*)d_in[9];
    const float* bih_r = (const float*)d_in[10];
    const float* bhh_r = (const float*)d_in[11];
    const float* fc_w  = (const float*)d_in[12];
    const float* fc_b  = (const float*)d_in[13];
    float* out = (float*)d_out;

    cudaFuncSetAttribute(input_gemm_hmma, cudaFuncAttributeMaxDynamicSharedMemorySize, GM_SMEM);
    cudaFuncSetAttribute(fused_rec_step, cudaFuncAttributeMaxDynamicSharedMemorySize, GM_SMEM);

    prep_kernel<<<(int)((PREP_TOTAL + 255) / 256), 256>>>(wih_f, wih_r, whh_f, whh_r,
                                                          bih_f, bhh_f, bih_r, bhh_r);
    masters_kernel<<<BH * 2, 256>>>(att, sents);
    build_slide<<<BH, 256>>>(logits, mask);

    // input GEMM: gatesX(2304x3072) = slide @ Wperm^T + bias
    input_gemm_hmma<<<dim3(2 * G4 / BN, BH * TT / 64), 256, GM_SMEM>>>();

    lstm0_kernel<<<(2 * BH * HH + 255) / 256, 256>>>();
    for (int s = 1; s < TT; s++) {
        fused_rec_step<<<dim3(G4 / BN, BH / 64, 2), 256, GM_SMEM>>>(s);
    }

    logits_rep_kernel<<<dim3(BATCH, DMODEL / 128), 128>>>(logits, mask);
    final_kernel<<<BATCH, 256>>>(fc_w, fc_b, out);
}

// round 17
// speedup vs baseline: 1.1381x; 1.1381x over previous
#include <cuda_runtime.h>
#include <cuda_fp16.h>
#include <math.h>
#include <stdint.h>

// ---------------- problem constants ----------------
#define BATCH  32
#define HEADS  12
#define SEQ    512
#define LHALF  256
#define DMODEL 768
#define HH     384          // hidden per direction
#define G4     1536         // 4*HH gates
#define DIN    1536         // 2*DMODEL LSTM input
#define BH     384          // BATCH*HEADS
#define TT     6            // SLIDER
#define EPSV   1e-9f

// ---------------- device scratch (no allocs allowed) ----------------
__device__ int    g_master[BH * 2];
__device__ __half g_gatesX[(size_t)BH * TT * 2 * G4];   // fp16, gate-interleaved cols (4*j+gate), bias folded
__device__ __half g_gtmp[(size_t)2 * BH * G4];          // fp16, per-step h @ whh^T
__device__ float  g_c[(size_t)2 * BH * HH];
__device__ float  g_compose[(size_t)BH * TT * DMODEL];
__device__ float  g_lrep[(size_t)BATCH * DMODEL];

// fp16 operands (weights gate-interleaved rows: 4*j+gate)
__device__ __half g_slide[(size_t)BH * TT * DIN];
__device__ __half g_wih[(size_t)2 * G4 * DIN];
__device__ __half g_whh[(size_t)2 * G4 * HH];
__device__ __half g_hb[(size_t)2 * BH * HH];       // [dir][n][j]
__device__ float  g_bias[2 * G4];                  // gate-interleaved

// ---------------- PTX helpers (baseline PTX only) ----------------
__device__ __forceinline__ uint32_t smem_u32(const void* p) {
    uint32_t a;
    asm("{ .reg .u64 t; cvta.to.shared.u64 t, %1; cvt.u32.u64 %0, t; }" : "=r"(a) : "l"(p));
    return a;
}

#define CP_ASYNC16(sm, gm) \
    asm volatile("cp.async.cg.shared.global [%0], [%1], 16;" :: "r"(sm), "l"(gm) : "memory")
#define CP_COMMIT() asm volatile("cp.async.commit_group;" ::: "memory")
#define CP_WAIT0()  asm volatile("cp.async.wait_group 0;" ::: "memory")

#define LDSM_X4(r0, r1, r2, r3, addr) \
    asm volatile("ldmatrix.sync.aligned.m8n8.x4.shared.b16 {%0,%1,%2,%3}, [%4];" \
        : "=r"(r0), "=r"(r1), "=r"(r2), "=r"(r3) : "r"(addr))

#define MMA_F16(c0, c1, c2, c3, a0, a1, a2, a3, b0, b1) \
    asm volatile("mma.sync.aligned.m16n8k16.row.col.f32.f16.f16.f32 " \
        "{%0,%1,%2,%3}, {%4,%5,%6,%7}, {%8,%9}, {%0,%1,%2,%3};" \
        : "+f"(c0), "+f"(c1), "+f"(c2), "+f"(c3) \
        : "r"(a0), "r"(a1), "r"(a2), "r"(a3), "r"(b0), "r"(b1))

// ---------------- helpers ----------------
__device__ __forceinline__ float sigf(float x) { return 1.0f / (1.0f + expf(-x)); }

__device__ __forceinline__ int window_start(int pos) {
    pos = min(max(pos, 1), LHALF - 2);
    int l = TT / 2;
    if (pos - TT / 2 <= 0) l = pos - 1;
    int r = TT - l;
    if (pos + r >= LHALF - 1) l = TT - (LHALF - pos - 2);
    return pos - l;
}

// ---------------- K1: masters (deep-MLP row sums) ----------------
__global__ void masters_kernel(const float* __restrict__ att, const int* __restrict__ sents) {
    int bid  = blockIdx.x;
    int half = bid & 1;
    int bh   = bid >> 1;
    int b    = bh / HEADS;

    __shared__ unsigned char seps[LHALF];
    __shared__ float rowsum[LHALF];

    int tid = threadIdx.x;
    {
        int j = half * LHALF + tid;
        seps[tid] = (sents[b * SEQ + j] == 102) ? 1 : 0;
    }
    __syncthreads();

    const float* base = att + ((size_t)bh * SEQ + (size_t)half * LHALF) * SEQ + (size_t)half * LHALF;

    int warp = tid >> 5, lane = tid & 31;
    #pragma unroll
    for (int rr = 0; rr < 32; rr += 4) {
        int row = warp * 32 + rr;
        const float4* r0 = (const float4*)(base + (size_t)(row + 0) * SEQ);
        const float4* r1 = (const float4*)(base + (size_t)(row + 1) * SEQ);
        const float4* r2 = (const float4*)(base + (size_t)(row + 2) * SEQ);
        const float4* r3 = (const float4*)(base + (size_t)(row + 3) * SEQ);
        float4 v0a = __ldg(r0 + lane), v0b = __ldg(r0 + lane + 32);
        float4 v1a = __ldg(r1 + lane), v1b = __ldg(r1 + lane + 32);
        float4 v2a = __ldg(r2 + lane), v2b = __ldg(r2 + lane + 32);
        float4 v3a = __ldg(r3 + lane), v3b = __ldg(r3 + lane + 32);

        int ja = lane * 4, jb = (lane + 32) * 4;
        float s0 = (seps[ja] ? EPSV : v0a.x) + (seps[ja+1] ? EPSV : v0a.y)
                 + (seps[ja+2] ? EPSV : v0a.z) + (seps[ja+3] ? EPSV : v0a.w)
                 + (seps[jb] ? EPSV : v0b.x) + (seps[jb+1] ? EPSV : v0b.y)
                 + (seps[jb+2] ? EPSV : v0b.z) + (seps[jb+3] ? EPSV : v0b.w);
        float s1 = (seps[ja] ? EPSV : v1a.x) + (seps[ja+1] ? EPSV : v1a.y)
                 + (seps[ja+2] ? EPSV : v1a.z) + (seps[ja+3] ? EPSV : v1a.w)
                 + (seps[jb] ? EPSV : v1b.x) + (seps[jb+1] ? EPSV : v1b.y)
                 + (seps[jb+2] ? EPSV : v1b.z) + (seps[jb+3] ? EPSV : v1b.w);
        float s2 = (seps[ja] ? EPSV : v2a.x) + (seps[ja+1] ? EPSV : v2a.y)
                 + (seps[ja+2] ? EPSV : v2a.z) + (seps[ja+3] ? EPSV : v2a.w)
                 + (seps[jb] ? EPSV : v2b.x) + (seps[jb+1] ? EPSV : v2b.y)
                 + (seps[jb+2] ? EPSV : v2b.z) + (seps[jb+3] ? EPSV : v2b.w);
        float s3 = (seps[ja] ? EPSV : v3a.x) + (seps[ja+1] ? EPSV : v3a.y)
                 + (seps[ja+2] ? EPSV : v3a.z) + (seps[ja+3] ? EPSV : v3a.w)
                 + (seps[jb] ? EPSV : v3b.x) + (seps[jb+1] ? EPSV : v3b.y)
                 + (seps[jb+2] ? EPSV : v3b.z) + (seps[jb+3] ? EPSV : v3b.w);

        #pragma unroll
        for (int off = 16; off > 0; off >>= 1) {
            s0 += __shfl_down_sync(0xffffffffu, s0, off);
            s1 += __shfl_down_sync(0xffffffffu, s1, off);
            s2 += __shfl_down_sync(0xffffffffu, s2, off);
            s3 += __shfl_down_sync(0xffffffffu, s3, off);
        }
        if (lane == 0) {
            rowsum[row]     = s0;
            rowsum[row + 1] = s1;
            rowsum[row + 2] = s2;
            rowsum[row + 3] = s3;
        }
    }
    __syncthreads();

    __shared__ float bv[LHALF];
    __shared__ int   bix[LHALF];
    bv[tid]  = rowsum[tid];
    bix[tid] = tid;
    __syncthreads();
    for (int off = 128; off > 0; off >>= 1) {
        if (tid < off) {
            float vo = bv[tid + off];
            int   io = bix[tid + off];
            if (vo > bv[tid] || (vo == bv[tid] && io < bix[tid])) { bv[tid] = vo; bix[tid] = io; }
        }
        __syncthreads();
    }
    if (tid == 0) g_master[bh * 2 + half] = bix[0];
}

// ---------------- K2: gather windows -> slide (fp16) ----------------
__global__ void build_slide(const float* __restrict__ logits, const int* __restrict__ mask) {
    int bh = blockIdx.x;
    int b  = bh / HEADS;
    __shared__ int sa, sb;
    if (threadIdx.x == 0) {
        sa = window_start(g_master[bh * 2 + 0]);
        sb = window_start(g_master[bh * 2 + 1]);
    }
    __syncthreads();

    for (int idx = threadIdx.x; idx < TT * DIN; idx += blockDim.x) {
        int t = idx / DIN, f = idx % DIN;
        float v;
        if (f < DMODEL) {
            int row = sa + t;
            v = (mask[b * SEQ + row] == 0) ? EPSV
                : logits[((size_t)b * SEQ + row) * DMODEL + f];
        } else {
            int row = LHALF + sb + t;
            v = (mask[b * SEQ + row] == 0) ? EPSV
                : logits[((size_t)b * SEQ + row) * DMODEL + (f - DMODEL)];
        }
        g_slide[(size_t)bh * (TT * DIN) + idx] = __float2half(v);
    }
}

// ---------------- K3: fused prep (vectorized fp16 weight convert + gate interleave + bias) ----------------
// Each thread handles 4 consecutive k-elements of one weight row (float4 -> 4x fp16, 8B store).
#define NW ((size_t)G4 * DIN)    // 2359296
#define NH ((size_t)G4 * HH)     // 589824
#define WQ ((2 * NW + 2 * NH) / 4)           // weight quads
#define PREP_TOTAL (WQ + 2 * G4)

__global__ void prep_kernel(const float* __restrict__ wih_f, const float* __restrict__ wih_r,
                            const float* __restrict__ whh_f, const float* __restrict__ whh_r,
                            const float* __restrict__ bihf, const float* __restrict__ bhhf,
                            const float* __restrict__ bihr, const float* __restrict__ bhhr) {
    size_t i = (size_t)blockIdx.x * blockDim.x + threadIdx.x;
    if (i >= PREP_TOTAL) return;
    if (i < WQ) {
        size_t e = i * 4;                    // element offset into concatenated weights
        const float* src;
        __half* dh;
        size_t off;
        int kdim;
        if (e < NW)               { src = wih_f; dh = g_wih;      off = e;                kdim = DIN; }
        else if (e < 2 * NW)      { src = wih_r; dh = g_wih + NW; off = e - NW;           kdim = DIN; }
        else if (e < 2 * NW + NH) { src = whh_f; dh = g_whh;      off = e - 2 * NW;       kdim = HH;  }
        else                      { src = whh_r; dh = g_whh + NH; off = e - 2 * NW - NH;  kdim = HH;  }
        size_t row = off / kdim, k = off % kdim;   // k is a multiple of 4 (kdim % 4 == 0)
        int gate = (int)(row / HH), j = (int)(row % HH);
        size_t drow = (size_t)(4 * j + gate);
        float4 v = *(const float4*)(src + off);
        __half2 h0 = __floats2half2_rn(v.x, v.y);
        __half2 h1 = __floats2half2_rn(v.z, v.w);
        __half2* dst = (__half2*)(dh + drow * kdim + k);
        dst[0] = h0;
        dst[1] = h1;
    } else {
        size_t q = i - WQ;                   // [0, 2*G4)
        int dir = (int)(q / G4);
        int r   = (int)(q % G4);
        int gate = r / HH, j = r % HH;
        float v = dir ? (bihr[r] + bhhr[r]) : (bihf[r] + bhhf[r]);
        g_bias[dir * G4 + 4 * j + gate] = v;
    }
}

// ---------------- GEMM core: tile 64(M) x 192(N), fp16 single product, 2 CTAs/SM ----------------
// Chunk layout: A(8KB) | B(24KB) = 32KB, double buffered.
#define BK          64
#define BN          192
#define A_CHUNK     8192           // 64 rows x 128B
#define B_CHUNK     24576          // 192 rows x 128B
#define BUF_BYTES   (A_CHUNK + B_CHUNK)       // 32768
#define GM_SMEM     (1024 + 2 * BUF_BYTES)    // 66560

__device__ __forceinline__ void gemm_core(
    const __half* A, const __half* B,
    int bm, int bn, int K, int NC,
    char* smem_raw, uint32_t tiles_u,
    int tid, int lane, int wm, int wn,
    float acc[2][6][4])
{
    int Kd8 = K >> 3;

    auto load_chunk = [&](int c, int buf) {
        int k0 = c * BK;
        uint32_t bufu = tiles_u + buf * BUF_BYTES;
        {
            const uint4* gp = (const uint4*)(A + (size_t)bm * K + k0);
            #pragma unroll
            for (int i = 0; i < 2; i++) {
                int u = tid + i * 256;
                int r = u >> 3, c16 = u & 7;
                const uint4* ga = gp + (size_t)r * Kd8 + c16;
                uint32_t off = (uint32_t)(r * 128 + c16 * 16);
                uint32_t sw = off ^ ((off >> 3) & 0x70);
                CP_ASYNC16(bufu + sw, ga);
            }
        }
        {
            const uint4* gp = (const uint4*)(B + (size_t)bn * K + k0);
            uint32_t tb = bufu + A_CHUNK;
            #pragma unroll
            for (int i = 0; i < 6; i++) {
                int u = tid + i * 256;
                int r = u >> 3, c16 = u & 7;
                const uint4* ga = gp + (size_t)r * Kd8 + c16;
                uint32_t off = (uint32_t)(r * 128 + c16 * 16);
                uint32_t sw = off ^ ((off >> 3) & 0x70);
                CP_ASYNC16(tb + sw, ga);
            }
        }
    };

    load_chunk(0, 0);
    CP_COMMIT();

    for (int c = 0; c < NC; c++) {
        CP_WAIT0();
        __syncthreads();
        if (c + 1 < NC) { load_chunk(c + 1, (c + 1) & 1); CP_COMMIT(); }

        uint32_t base = tiles_u + (c & 1) * BUF_BYTES;
        uint32_t a_base = base;
        uint32_t b_base = base + A_CHUNK;

        #pragma unroll
        for (int ks = 0; ks < 4; ks++) {
            uint32_t a[2][4];
            #pragma unroll
            for (int mt = 0; mt < 2; mt++) {
                uint32_t r = wm + mt * 16 + (lane & 15);
                uint32_t coloff = ks * 32 + ((lane >> 4) & 1) * 16;
                uint32_t off = r * 128 + coloff;
                uint32_t sw = off ^ ((off >> 3) & 0x70);
                LDSM_X4(a[mt][0], a[mt][1], a[mt][2], a[mt][3], a_base + sw);
            }
            uint32_t b[6][2];
            #pragma unroll
            for (int h = 0; h < 3; h++) {
                uint32_t r = wn + h * 16 + (lane & 7) + ((lane >> 4) << 3);
                uint32_t coloff = ks * 32 + ((lane >> 3) & 1) * 16;
                uint32_t off = r * 128 + coloff;
                uint32_t sw = off ^ ((off >> 3) & 0x70);
                uint32_t r0, r1, r2, r3;
                LDSM_X4(r0, r1, r2, r3, b_base + sw);
                b[2 * h][0] = r0; b[2 * h][1] = r1;
                b[2 * h + 1][0] = r2; b[2 * h + 1][1] = r3;
            }
            #pragma unroll
            for (int mt = 0; mt < 2; mt++)
                #pragma unroll
                for (int nt = 0; nt < 6; nt++)
                    MMA_F16(acc[mt][nt][0], acc[mt][nt][1], acc[mt][nt][2], acc[mt][nt][3],
                            a[mt][0], a[mt][1], a[mt][2], a[mt][3],
                            b[nt][0], b[nt][1]);
        }
        __syncthreads();
    }
}

// ---------------- K4: input GEMM (tile 64x192, 2 CTAs/SM) ----------------
__global__ __launch_bounds__(256, 2) void input_gemm_hmma() {
    extern __shared__ char smem_raw[];
    uint32_t smem_u = smem_u32(smem_raw);
    uint32_t tiles_u = (smem_u + 1023) & ~1023u;

    int tid = threadIdx.x, wid = tid >> 5, lane = tid & 31;
    int wm = (wid & 1) * 32, wn = (wid >> 1) * 48;
    int bm = blockIdx.y * 64;
    int bn = blockIdx.x * BN;

    float acc[2][6][4];
    #pragma unroll
    for (int i = 0; i < 2; i++)
        #pragma unroll
        for (int j = 0; j < 6; j++)
            #pragma unroll
            for (int q = 0; q < 4; q++) acc[i][j][q] = 0.0f;

    gemm_core(g_slide, g_wih, bm, bn, DIN, DIN / BK,
              smem_raw, tiles_u, tid, lane, wm, wn, acc);

    #pragma unroll
    for (int mt = 0; mt < 2; mt++) {
        #pragma unroll
        for (int nt = 0; nt < 6; nt++) {
            int row = bm + wm + mt * 16 + (lane >> 2);
            int col = bn + wn + nt * 8 + (lane & 3) * 2;
            float b0 = g_bias[col], b1 = g_bias[col + 1];
            __half2 v0 = __floats2half2_rn(acc[mt][nt][0] + b0, acc[mt][nt][1] + b1);
            __half2 v1 = __floats2half2_rn(acc[mt][nt][2] + b0, acc[mt][nt][3] + b1);
            *(__half2*)(g_gatesX + (size_t)row * (2 * G4) + col) = v0;
            *(__half2*)(g_gatesX + (size_t)(row + 8) * (2 * G4) + col) = v1;
        }
    }
}

// ---------------- K5: recurrent GEMM  gtmp[dir] = h[dir] @ whh[dir]^T ----------------
__global__ __launch_bounds__(256, 2) void rec_gemm_hmma() {
    extern __shared__ char smem_raw[];
    uint32_t smem_u = smem_u32(smem_raw);
    uint32_t tiles_u = (smem_u + 1023) & ~1023u;

    int z = blockIdx.z;
    const __half* A = g_hb + (size_t)z * BH * HH;
    const __half* B = g_whh + (size_t)z * G4 * HH;
    __half* C = g_gtmp + (size_t)z * BH * G4;

    int tid = threadIdx.x, wid = tid >> 5, lane = tid & 31;
    int wm = (wid & 1) * 32, wn = (wid >> 1) * 48;
    int bm = blockIdx.y * 64;
    int bn = blockIdx.x * BN;

    float acc[2][6][4];
    #pragma unroll
    for (int i = 0; i < 2; i++)
        #pragma unroll
        for (int j = 0; j < 6; j++)
            #pragma unroll
            for (int q = 0; q < 4; q++) acc[i][j][q] = 0.0f;

    gemm_core(A, B, bm, bn, HH, HH / BK,
              smem_raw, tiles_u, tid, lane, wm, wn, acc);

    #pragma unroll
    for (int mt = 0; mt < 2; mt++) {
        #pragma unroll
        for (int nt = 0; nt < 6; nt++) {
            int row = bm + wm + mt * 16 + (lane >> 2);
            int col = bn + wn + nt * 8 + (lane & 3) * 2;
            __half2 v0 = __floats2half2_rn(acc[mt][nt][0], acc[mt][nt][1]);
            __half2 v1 = __floats2half2_rn(acc[mt][nt][2], acc[mt][nt][3]);
            *(__half2*)(C + (size_t)row * G4 + col) = v0;
            *(__half2*)(C + (size_t)(row + 8) * G4 + col) = v1;
        }
    }
}

// ---------------- K6: per-step LSTM pointwise (fp16 half2 gate reads) ----------------
__global__ void lstm_point(int s) {
    int idx = blockIdx.x * blockDim.x + threadIdx.x;
    if (idx >= 2 * BH * HH) return;
    int dir = idx / (BH * HH);
    int r   = idx % (BH * HH);
    int n   = r / HH;
    int j   = r % HH;
    int t   = dir ? (TT - 1 - s) : s;

    const __half2* gp = (const __half2*)(g_gatesX + ((size_t)(n * TT + t)) * (2 * G4)
                                         + (size_t)dir * G4 + 4 * j);
    float2 p0 = __half22float2(gp[0]);
    float2 p1 = __half22float2(gp[1]);
    float gi = p0.x, gf = p0.y, gg = p1.x, go = p1.y;

    float c;
    if (s == 0) {
        c = sigf(gi) * tanhf(gg);
    } else {
        const __half2* tp = (const __half2*)(g_gtmp + (size_t)dir * BH * G4 + (size_t)n * G4 + 4 * j);
        float2 t0 = __half22float2(tp[0]);
        float2 t1 = __half22float2(tp[1]);
        gi += t0.x; gf += t0.y; gg += t1.x; go += t1.y;
        c = sigf(gf) * g_c[idx] + sigf(gi) * tanhf(gg);
    }
    float h = sigf(go) * tanhf(c);
    g_c[idx] = c;
    g_hb[idx] = __float2half(h);
    g_compose[((size_t)n * TT + t) * DMODEL + dir * HH + j] = h;
}

// ---------------- K7: logits_rep (parallelized, deep ILP) ----------------
__global__ void logits_rep_kernel(const float* __restrict__ logits, const int* __restrict__ mask) {
    int b = blockIdx.x;
    int d = blockIdx.y * 128 + threadIdx.x;
    int tid = threadIdx.x;

    __shared__ unsigned char repl[SEQ];
    for (int i = tid; i < SEQ; i += blockDim.x) repl[i] = 0;
    __syncthreads();
    if (tid < 2 * HEADS) {
        int h = tid >> 1, half = tid & 1;
        int st = window_start(g_master[(b * HEADS + h) * 2 + half]);
        int base = half * LHALF + st;
        for (int k = 0; k < TT; k++) repl[base + k] = 1;
    }
    __syncthreads();
    for (int sPos = tid; sPos < SEQ; sPos += blockDim.x)
        repl[sPos] = (repl[sPos] && mask[b * SEQ + sPos] == 0) ? 1 : 0;
    __syncthreads();

    float a0 = 0.f, a1 = 0.f, a2 = 0.f, a3 = 0.f;
    const float* lp = logits + (size_t)b * SEQ * DMODEL + d;
    for (int sPos = 0; sPos < SEQ; sPos += 8) {
        float v0 = __ldg(lp + (size_t)(sPos + 0) * DMODEL);
        float v1 = __ldg(lp + (size_t)(sPos + 1) * DMODEL);
        float v2 = __ldg(lp + (size_t)(sPos + 2) * DMODEL);
        float v3 = __ldg(lp + (size_t)(sPos + 3) * DMODEL);
        float v4 = __ldg(lp + (size_t)(sPos + 4) * DMODEL);
        float v5 = __ldg(lp + (size_t)(sPos + 5) * DMODEL);
        float v6 = __ldg(lp + (size_t)(sPos + 6) * DMODEL);
        float v7 = __ldg(lp + (size_t)(sPos + 7) * DMODEL);
        a0 += repl[sPos]     ? EPSV : v0;
        a1 += repl[sPos + 1] ? EPSV : v1;
        a2 += repl[sPos + 2] ? EPSV : v2;
        a3 += repl[sPos + 3] ? EPSV : v3;
        a0 += repl[sPos + 4] ? EPSV : v4;
        a1 += repl[sPos + 5] ? EPSV : v5;
        a2 += repl[sPos + 6] ? EPSV : v6;
        a3 += repl[sPos + 7] ? EPSV : v7;
    }
    g_lrep[(size_t)b * DMODEL + d] = (a0 + a1 + a2 + a3) * (1.0f / (float)SEQ);
}

// ---------------- K8: final FC + softmax ----------------
__global__ void final_kernel(const float* __restrict__ fcw, const float* __restrict__ fcb,
                             float* __restrict__ out) {
    int b = blockIdx.x;
    int tid = threadIdx.x;
    const int NF = DMODEL * (HEADS + 1);
    float a0 = 0.0f, a1 = 0.0f;

    for (int j = tid; j < NF; j += 256) {
        float x;
        if (j < HEADS * DMODEL) {
            int h = j / DMODEL, d = j % DMODEL;
            int n = b * HEADS + h;
            const float* cp = g_compose + (size_t)n * TT * DMODEL + d;
            float s = 0.0f;
            #pragma unroll
            for (int t = 0; t < TT; t++) s += cp[(size_t)t * DMODEL];
            x = s * (1.0f / (float)TT);
        } else {
            x = g_lrep[(size_t)b * DMODEL + (j - HEADS * DMODEL)];
        }
        a0 += x * fcw[j];
        a1 += x * fcw[NF + j];
    }

    __shared__ float s0[256], s1[256];
    s0[tid] = a0; s1[tid] = a1;
    __syncthreads();
    for (int off = 128; off > 0; off >>= 1) {
        if (tid < off) { s0[tid] += s0[tid + off]; s1[tid] += s1[tid + off]; }
        __syncthreads();
    }
    if (tid == 0) {
        float l0 = s0[0] + fcb[0], l1 = s1[0] + fcb[1];
        float m = fmaxf(l0, l1);
        float e0 = expf(l0 - m), e1 = expf(l1 - m);
        float inv = 1.0f / (e0 + e1);
        out[b * 2 + 0] = e0 * inv;
        out[b * 2 + 1] = e1 * inv;
    }
}

// ---------------- launch ----------------
extern "C" void kernel_launch(void* const* d_in, const int* in_sizes, int n_in,
                              void* d_out, int out_size) {
    const int*   sents = (const int*)d_in[0];
    const float* att   = (const float*)d_in[1];
    const float* logits= (const float*)d_in[2];
    const int*   mask  = (const int*)d_in[3];
    const float* wih_f = (const float*)d_in[4];
    const float* whh_f = (const float*)d_in[5];
    const float* bih_f = (const float*)d_in[6];
    const float* bhh_f = (const float*)d_in[7];
    const float* wih_r = (const float*)d_in[8];
    const float* whh_r = (const float*)d_in[9];
    const float* bih_r = (const float*)d_in[10];
    const float* bhh_r = (const float*)d_in[11];
    const float* fc_w  = (const float*)d_in[12];
    const float* fc_b  = (const float*)d_in[13];
    float* out = (float*)d_out;

    cudaFuncSetAttribute(input_gemm_hmma, cudaFuncAttributeMaxDynamicSharedMemorySize, GM_SMEM);
    cudaFuncSetAttribute(rec_gemm_hmma, cudaFuncAttributeMaxDynamicSharedMemorySize, GM_SMEM);

    prep_kernel<<<(int)((PREP_TOTAL + 255) / 256), 256>>>(wih_f, wih_r, whh_f, whh_r,
                                                          bih_f, bhh_f, bih_r, bhh_r);
    masters_kernel<<<BH * 2, 256>>>(att, sents);
    build_slide<<<BH, 256>>>(logits, mask);

    // input GEMM: gatesX(2304x3072) = slide @ Wperm^T + bias
    input_gemm_hmma<<<dim3(2 * G4 / BN, BH * TT / 64), 256, GM_SMEM>>>();

    for (int s = 0; s < TT; s++) {
        lstm_point<<<(2 * BH * HH + 255) / 256, 256>>>(s);
        if (s < TT - 1) {
            rec_gemm_hmma<<<dim3(G4 / BN, BH / 64, 2), 256, GM_SMEM>>>();
        }
    }

    logits_rep_kernel<<<dim3(BATCH, DMODEL / 128), 128>>>(logits, mask);
    final_kernel<<<BATCH, 256>>>(fc_w, fc_b, out);
}